// round 3
// baseline (speedup 1.0000x reference)
#include <cuda_runtime.h>

#define N_MAX   100000
#define NH      4
#define HID     64
#define INDIM   128
#define REL     50
#define PD      16

// ---------------- scratch (device globals; no allocation allowed) -------------
__device__ __align__(16) float d_w[3 * REL * NH];      // exp(leaky(rel_emb@W_pred)) per layer
__device__ __align__(16) float d_h0[N_MAX * NH];       // MLP output (N,4)
__device__ __align__(16) float d_num0[N_MAX * NH];     // layer-0 numerators
__device__ int   d_cnt[N_MAX * REL];                   // per-node incoming type histogram
__device__ float d_S[N_MAX * REL];                     // per-node per-type sum of scalar h[src]
__device__ float d_h1s[N_MAX];                         // scalar h after layer 0
__device__ float d_h2s[N_MAX];                         // scalar h after layer 1

// ---------------- tiny table kernel -------------------------------------------
__global__ void k_tables(const float* __restrict__ rel_emb,
                         const float* __restrict__ W_pred) {
    int l = blockIdx.x;               // 0..2
    int tid = threadIdx.x;            // 0..199
    if (tid >= REL * NH) return;
    int t = tid >> 2, h = tid & 3;
    float acc = 0.f;
#pragma unroll
    for (int p = 0; p < PD; ++p)
        acc += rel_emb[t * PD + p] * W_pred[l * PD * NH + p * NH + h];
    float e = acc > 0.f ? acc : 0.2f * acc;
    d_w[l * REL * NH + tid] = expf(e);
}

// ---------------- zero kernels ------------------------------------------------
__global__ void k_zero0(int n) {
    int tot = n * REL;
    for (int i = blockIdx.x * blockDim.x + threadIdx.x; i < tot;
         i += gridDim.x * blockDim.x) {
        d_cnt[i] = 0;
        if (i < n * NH) d_num0[i] = 0.f;
    }
}
__global__ void k_zeroS(int n) {
    int tot = n * REL;
    for (int i = blockIdx.x * blockDim.x + threadIdx.x; i < tot;
         i += gridDim.x * blockDim.x)
        d_S[i] = 0.f;
}

// ---------------- node MLP: h0[n,h] = relu(x@W1[h]^T + b1[h]) @ W2[h] + b2[h] --
// grid: (ceil(n/64), 4 heads), block 128. Tiles: 64 nodes x 64 hid, K chunks of 64.
__global__ void __launch_bounds__(128) k_mlp(
    const float* __restrict__ inputs, const float* __restrict__ W1,
    const float* __restrict__ b1, const float* __restrict__ W2,
    const float* __restrict__ b2, int n) {
    __shared__ float As[64][65];   // [k][node]
    __shared__ float Bs[64][68];   // [k][hid]  (row = 272B, 16B aligned)
    __shared__ float red[8][64];

    const int h  = blockIdx.y;
    const int n0 = blockIdx.x * 64;
    const int tid = threadIdx.x;
    const int tx = tid & 15;       // node group (16)
    const int ty = tid >> 4;       // hid group (8)
    const float* W1h = W1 + h * HID * INDIM;

    float acc[4][8];
#pragma unroll
    for (int i = 0; i < 4; ++i)
#pragma unroll
        for (int j = 0; j < 8; ++j) acc[i][j] = 0.f;

    for (int kc = 0; kc < INDIM; kc += 64) {
        // load A tile (transposed) : 64 nodes x 64 k
        {
            int nl = tid >> 1;
            int kb = (tid & 1) * 32;
            int node = n0 + nl;
#pragma unroll
            for (int j = 0; j < 32; j += 4) {
                float4 v = make_float4(0.f, 0.f, 0.f, 0.f);
                if (node < n)
                    v = *(const float4*)&inputs[(size_t)node * INDIM + kc + kb + j];
                As[kb + j + 0][nl] = v.x;
                As[kb + j + 1][nl] = v.y;
                As[kb + j + 2][nl] = v.z;
                As[kb + j + 3][nl] = v.w;
            }
#pragma unroll
            for (int j = 0; j < 32; j += 4) {
                float4 v = *(const float4*)&W1h[nl * INDIM + kc + kb + j];
                Bs[kb + j + 0][nl] = v.x;
                Bs[kb + j + 1][nl] = v.y;
                Bs[kb + j + 2][nl] = v.z;
                Bs[kb + j + 3][nl] = v.w;
            }
        }
        __syncthreads();
#pragma unroll 8
        for (int k = 0; k < 64; ++k) {
            float a[4], b[8];
#pragma unroll
            for (int i = 0; i < 4; ++i) a[i] = As[k][tx + 16 * i];
#pragma unroll
            for (int j = 0; j < 8; ++j) b[j] = Bs[k][ty * 8 + j];
#pragma unroll
            for (int i = 0; i < 4; ++i)
#pragma unroll
                for (int j = 0; j < 8; ++j) acc[i][j] += a[i] * b[j];
        }
        __syncthreads();
    }

    // epilogue: relu(+b1) * W2, reduce over hid
    float partial[4];
#pragma unroll
    for (int i = 0; i < 4; ++i) {
        float s = 0.f;
#pragma unroll
        for (int j = 0; j < 8; ++j) {
            int hid = ty * 8 + j;
            float v = acc[i][j] + b1[h * HID + hid];
            v = v > 0.f ? v : 0.f;
            s += v * W2[h * HID + hid];
        }
        partial[i] = s;
    }
#pragma unroll
    for (int i = 0; i < 4; ++i) red[ty][tx + 16 * i] = partial[i];
    __syncthreads();
    if (tid < 64) {
        float s = 0.f;
#pragma unroll
        for (int g = 0; g < 8; ++g) s += red[g][tid];
        int node = n0 + tid;
        if (node < n) d_h0[node * NH + h] = s + b2[h];
    }
}

// ---------------- layer 0 edge pass: cnt histogram + per-head numerators ------
__global__ void k_edge0(const int* __restrict__ et, const int* __restrict__ src,
                        const int* __restrict__ dst, int e) {
    __shared__ float w0[REL * NH];
    if (threadIdx.x < REL * NH) w0[threadIdx.x] = d_w[threadIdx.x];
    __syncthreads();
    int i = blockIdx.x * blockDim.x + threadIdx.x;
    if (i >= e) return;
    int t = et[i], s = src[i], d = dst[i];
    atomicAdd(&d_cnt[d * REL + t], 1);
    float4 hs = *(const float4*)&d_h0[s * NH];
    const float* w = &w0[t * NH];
    atomicAdd(&d_num0[d * NH + 0], w[0] * hs.x);
    atomicAdd(&d_num0[d * NH + 1], w[1] * hs.y);
    atomicAdd(&d_num0[d * NH + 2], w[2] * hs.z);
    atomicAdd(&d_num0[d * NH + 3], w[3] * hs.w);
}

// ---------------- layers 1/2 edge pass: scalar scatter ------------------------
__global__ void k_edgeS(const int* __restrict__ et, const int* __restrict__ src,
                        const int* __restrict__ dst, int e, int which) {
    int i = blockIdx.x * blockDim.x + threadIdx.x;
    if (i >= e) return;
    const float* hv = which ? d_h2s : d_h1s;
    atomicAdd(&d_S[dst[i] * REL + et[i]], hv[src[i]]);
}

// ---------------- combine kernels (warp per node) ------------------------------
__device__ __forceinline__ float warp_sum(float v) {
#pragma unroll
    for (int o = 16; o; o >>= 1) v += __shfl_down_sync(0xffffffffu, v, o);
    return v;
}

// layer 0: den from cnt, num0 explicit; h1s = mean_h relu(num/den)
__global__ void k_combine0(int n) {
    __shared__ float w[REL * NH];
    if (threadIdx.x < REL * NH) w[threadIdx.x] = d_w[threadIdx.x];
    __syncthreads();
    int gw = (blockIdx.x * blockDim.x + threadIdx.x) >> 5;
    int lane = threadIdx.x & 31;
    if (gw >= n) return;
    float accD[NH] = {0.f, 0.f, 0.f, 0.f};
    {
        float c = (float)d_cnt[gw * REL + lane];
#pragma unroll
        for (int h = 0; h < NH; ++h) accD[h] += c * w[lane * NH + h];
    }
    if (lane < REL - 32) {
        int t2 = lane + 32;
        float c = (float)d_cnt[gw * REL + t2];
#pragma unroll
        for (int h = 0; h < NH; ++h) accD[h] += c * w[t2 * NH + h];
    }
#pragma unroll
    for (int h = 0; h < NH; ++h) accD[h] = warp_sum(accD[h]);
    if (lane == 0) {
        float4 num = *(const float4*)&d_num0[gw * NH];
        float nv[4] = {num.x, num.y, num.z, num.w};
        float s = 0.f;
#pragma unroll
        for (int h = 0; h < NH; ++h) {
            float r = (accD[h] > 0.f) ? nv[h] / accD[h] : 0.f;
            s += (r > 0.f ? r : 0.f);
        }
        d_h1s[gw] = 0.25f * s;
    }
}

// layers 1/2: num from S table, den from cnt
__global__ void k_combine12(int n, int layer,
                            const float* __restrict__ centrality,
                            const float* __restrict__ gamma,
                            const float* __restrict__ beta,
                            float* __restrict__ out, int final_layer) {
    __shared__ float w[REL * NH];
    if (threadIdx.x < REL * NH) w[threadIdx.x] = d_w[layer * REL * NH + threadIdx.x];
    __syncthreads();
    int gw = (blockIdx.x * blockDim.x + threadIdx.x) >> 5;
    int lane = threadIdx.x & 31;
    if (gw >= n) return;
    float accD[NH] = {0.f, 0.f, 0.f, 0.f};
    float accN[NH] = {0.f, 0.f, 0.f, 0.f};
    {
        float c = (float)d_cnt[gw * REL + lane];
        float sv = d_S[gw * REL + lane];
#pragma unroll
        for (int h = 0; h < NH; ++h) {
            float wv = w[lane * NH + h];
            accD[h] += c * wv;
            accN[h] += sv * wv;
        }
    }
    if (lane < REL - 32) {
        int t2 = lane + 32;
        float c = (float)d_cnt[gw * REL + t2];
        float sv = d_S[gw * REL + t2];
#pragma unroll
        for (int h = 0; h < NH; ++h) {
            float wv = w[t2 * NH + h];
            accD[h] += c * wv;
            accN[h] += sv * wv;
        }
    }
#pragma unroll
    for (int h = 0; h < NH; ++h) {
        accD[h] = warp_sum(accD[h]);
        accN[h] = warp_sum(accN[h]);
    }
    if (lane == 0) {
        if (!final_layer) {
            float s = 0.f;
#pragma unroll
            for (int h = 0; h < NH; ++h) {
                float r = (accD[h] > 0.f) ? accN[h] / accD[h] : 0.f;
                s += (r > 0.f ? r : 0.f);
            }
            d_h2s[gw] = 0.25f * s;
        } else {
            float c = centrality[gw];
            float s = 0.f;
#pragma unroll
            for (int h = 0; h < NH; ++h) {
                float r = (accD[h] > 0.f) ? accN[h] / accD[h] : 0.f;
                r = (r > 0.f ? r : 0.f);                  // relu -> logits
                s += (c * gamma[h] + beta[h]) * r;
            }
            float v = 0.25f * s;
            out[gw] = (v > 0.f) ? v : 0.01f * v;          // leaky_relu(mean, 0.01)
        }
    }
}

// ---------------- launch -------------------------------------------------------
extern "C" void kernel_launch(void* const* d_in, const int* in_sizes, int n_in,
                              void* d_out, int out_size) {
    const float* inputs     = (const float*)d_in[0];
    const float* centrality = (const float*)d_in[1];
    const float* W1         = (const float*)d_in[2];
    const float* b1         = (const float*)d_in[3];
    const float* W2         = (const float*)d_in[4];
    const float* b2         = (const float*)d_in[5];
    const float* rel_emb    = (const float*)d_in[6];
    const float* W_pred     = (const float*)d_in[7];
    const float* gamma      = (const float*)d_in[8];
    const float* beta       = (const float*)d_in[9];
    const int*   et         = (const int*)d_in[10];
    const int*   src        = (const int*)d_in[11];
    const int*   dst        = (const int*)d_in[12];

    const int n = in_sizes[1];          // N  (centrality element count)
    const int e = in_sizes[10];         // E  (edge_types element count)
    float* out = (float*)d_out;

    const int EB = (e + 255) / 256;
    const int NB = (n + 7) / 8;         // warp-per-node combine blocks

    k_tables<<<3, 256>>>(rel_emb, W_pred);
    k_zero0<<<4096, 256>>>(n);
    k_mlp<<<dim3((n + 63) / 64, NH), 128>>>(inputs, W1, b1, W2, b2, n);

    // layer 0
    k_edge0<<<EB, 256>>>(et, src, dst, e);
    k_combine0<<<NB, 256>>>(n);

    // layer 1
    k_zeroS<<<4096, 256>>>(n);
    k_edgeS<<<EB, 256>>>(et, src, dst, e, 0);
    k_combine12<<<NB, 256>>>(n, 1, centrality, gamma, beta, out, 0);

    // layer 2 + epilogue
    k_zeroS<<<4096, 256>>>(n);
    k_edgeS<<<EB, 256>>>(et, src, dst, e, 1);
    k_combine12<<<NB, 256>>>(n, 2, centrality, gamma, beta, out, 1);
}

// round 5
// speedup vs baseline: 1.3367x; 1.3367x over previous
#include <cuda_runtime.h>

#define N_MAX   100000
#define NH      4
#define HID     64
#define INDIM   128
#define REL     50
#define PD      16
#define CW      13          // ceil(REL/4) packed-count words per node

// ---------------- scratch (device globals; no allocation allowed) -------------
__device__ __align__(16) float  d_w[3 * REL * NH];   // exp(leaky(rel_emb@W_pred)) per layer
__device__ __align__(16) float4 d_h0[N_MAX];         // MLP output (N,4)
__device__ unsigned d_cntp[N_MAX * CW];              // byte-packed type histogram (4 types/word)
__device__ __align__(16) float4 d_num0[N_MAX];
__device__ __align__(16) float4 d_num1[N_MAX];
__device__ __align__(16) float4 d_num2[N_MAX];
__device__ __align__(16) float4 d_den1[N_MAX];
__device__ __align__(16) float4 d_den2[N_MAX];
__device__ float d_h1s[N_MAX];                       // scalar h after layer 0
__device__ float d_h2s[N_MAX];                       // scalar h after layer 1

// ---------------- tiny table kernel -------------------------------------------
__global__ void k_tables(const float* __restrict__ rel_emb,
                         const float* __restrict__ W_pred) {
    int l = blockIdx.x;               // 0..2
    int tid = threadIdx.x;
    if (tid >= REL * NH) return;
    int t = tid >> 2, h = tid & 3;
    float acc = 0.f;
#pragma unroll
    for (int p = 0; p < PD; ++p)
        acc += rel_emb[t * PD + p] * W_pred[l * PD * NH + p * NH + h];
    float e = acc > 0.f ? acc : 0.2f * acc;
    d_w[l * REL * NH + tid] = expf(e);
}

// ---------------- zero kernel (cnt + all numerators) --------------------------
__global__ void k_zero(int n) {
    int tot = n * CW;
    int stride = gridDim.x * blockDim.x;
    for (int i = blockIdx.x * blockDim.x + threadIdx.x; i < tot; i += stride)
        d_cntp[i] = 0u;
    float4 z = make_float4(0.f, 0.f, 0.f, 0.f);
    for (int i = blockIdx.x * blockDim.x + threadIdx.x; i < n; i += stride) {
        d_num0[i] = z; d_num1[i] = z; d_num2[i] = z;
    }
}

// ---------------- node MLP: h0[n,h] = relu(x@W1[h]^T + b1[h]) @ W2[h] + b2[h] --
__global__ void __launch_bounds__(128) k_mlp(
    const float* __restrict__ inputs, const float* __restrict__ W1,
    const float* __restrict__ b1, const float* __restrict__ W2,
    const float* __restrict__ b2, int n) {
    __shared__ float As[64][65];   // [k][node]
    __shared__ float Bs[64][68];   // [k][hid]
    __shared__ float red[8][64];

    const int h  = blockIdx.y;
    const int n0 = blockIdx.x * 64;
    const int tid = threadIdx.x;
    const int tx = tid & 15;
    const int ty = tid >> 4;
    const float* W1h = W1 + h * HID * INDIM;

    float acc[4][8];
#pragma unroll
    for (int i = 0; i < 4; ++i)
#pragma unroll
        for (int j = 0; j < 8; ++j) acc[i][j] = 0.f;

    for (int kc = 0; kc < INDIM; kc += 64) {
        {
            int nl = tid >> 1;
            int kb = (tid & 1) * 32;
            int node = n0 + nl;
#pragma unroll
            for (int j = 0; j < 32; j += 4) {
                float4 v = make_float4(0.f, 0.f, 0.f, 0.f);
                if (node < n)
                    v = *(const float4*)&inputs[(size_t)node * INDIM + kc + kb + j];
                As[kb + j + 0][nl] = v.x;
                As[kb + j + 1][nl] = v.y;
                As[kb + j + 2][nl] = v.z;
                As[kb + j + 3][nl] = v.w;
            }
#pragma unroll
            for (int j = 0; j < 32; j += 4) {
                float4 v = *(const float4*)&W1h[nl * INDIM + kc + kb + j];
                Bs[kb + j + 0][nl] = v.x;
                Bs[kb + j + 1][nl] = v.y;
                Bs[kb + j + 2][nl] = v.z;
                Bs[kb + j + 3][nl] = v.w;
            }
        }
        __syncthreads();
#pragma unroll 8
        for (int k = 0; k < 64; ++k) {
            float a[4], b[8];
#pragma unroll
            for (int i = 0; i < 4; ++i) a[i] = As[k][tx + 16 * i];
#pragma unroll
            for (int j = 0; j < 8; ++j) b[j] = Bs[k][ty * 8 + j];
#pragma unroll
            for (int i = 0; i < 4; ++i)
#pragma unroll
                for (int j = 0; j < 8; ++j) acc[i][j] += a[i] * b[j];
        }
        __syncthreads();
    }

    float partial[4];
#pragma unroll
    for (int i = 0; i < 4; ++i) {
        float s = 0.f;
#pragma unroll
        for (int j = 0; j < 8; ++j) {
            int hid = ty * 8 + j;
            float v = acc[i][j] + b1[h * HID + hid];
            v = v > 0.f ? v : 0.f;
            s += v * W2[h * HID + hid];
        }
        partial[i] = s;
    }
#pragma unroll
    for (int i = 0; i < 4; ++i) red[ty][tx + 16 * i] = partial[i];
    __syncthreads();
    if (tid < 64) {
        float s = 0.f;
#pragma unroll
        for (int g = 0; g < 8; ++g) s += red[g][tid];
        int node = n0 + tid;
        if (node < n) ((float*)d_h0)[node * NH + h] = s + b2[h];
    }
}

// ---------------- layer 0 edge pass: packed histogram + vec4 numerators -------
__global__ void k_edge0(const int* __restrict__ et, const int* __restrict__ src,
                        const int* __restrict__ dst, int e) {
    __shared__ float4 w0[REL];
    if (threadIdx.x < REL) w0[threadIdx.x] = ((const float4*)d_w)[threadIdx.x];
    __syncthreads();
    int i = blockIdx.x * blockDim.x + threadIdx.x;
    if (i >= e) return;
    int t = et[i], s = src[i], d = dst[i];
    atomicAdd(&d_cntp[d * CW + (t >> 2)], 1u << (8 * (t & 3)));
    float4 hs = d_h0[s];
    float4 wv = w0[t];
    atomicAdd(&d_num0[d],
              make_float4(wv.x * hs.x, wv.y * hs.y, wv.z * hs.z, wv.w * hs.w));
}

// ---------------- layers 1/2 edge pass: scalar gather, vec4 scatter -----------
__global__ void k_edgeS(const int* __restrict__ et, const int* __restrict__ src,
                        const int* __restrict__ dst, int e, int which) {
    __shared__ float4 w[REL];
    if (threadIdx.x < REL)
        w[threadIdx.x] = ((const float4*)d_w)[(which ? 2 : 1) * REL + threadIdx.x];
    __syncthreads();
    int i = blockIdx.x * blockDim.x + threadIdx.x;
    if (i >= e) return;
    int t = et[i], d = dst[i];
    const float* hv = which ? d_h2s : d_h1s;
    float hs = hv[src[i]];
    float4 wv = w[t];
    float4* numl = which ? d_num2 : d_num1;
    atomicAdd(&numl[d], make_float4(wv.x * hs, wv.y * hs, wv.z * hs, wv.w * hs));
}

// ---------------- combine 0: dens for ALL layers from histogram + h1s ---------
__global__ void k_combine0(int n) {
    __shared__ float4 w[3 * REL];
    if (threadIdx.x < 3 * REL) w[threadIdx.x] = ((const float4*)d_w)[threadIdx.x];
    __syncthreads();
    int i = blockIdx.x * blockDim.x + threadIdx.x;
    if (i >= n) return;
    float4 de0 = make_float4(0.f, 0.f, 0.f, 0.f);
    float4 de1 = de0, de2 = de0;
#pragma unroll
    for (int j = 0; j < CW; ++j) {
        unsigned cw = d_cntp[i * CW + j];
#pragma unroll
        for (int b = 0; b < 4; ++b) {
            int t = j * 4 + b;
            if (t >= REL) break;
            float c = (float)((cw >> (8 * b)) & 0xffu);
            float4 w0 = w[t], w1 = w[REL + t], w2 = w[2 * REL + t];
            de0.x += c * w0.x; de0.y += c * w0.y; de0.z += c * w0.z; de0.w += c * w0.w;
            de1.x += c * w1.x; de1.y += c * w1.y; de1.z += c * w1.z; de1.w += c * w1.w;
            de2.x += c * w2.x; de2.y += c * w2.y; de2.z += c * w2.z; de2.w += c * w2.w;
        }
    }
    d_den1[i] = de1;
    d_den2[i] = de2;
    float4 nu = d_num0[i];
    float s = 0.f;
    {
        float r;
        r = de0.x > 0.f ? nu.x / de0.x : 0.f; s += r > 0.f ? r : 0.f;
        r = de0.y > 0.f ? nu.y / de0.y : 0.f; s += r > 0.f ? r : 0.f;
        r = de0.z > 0.f ? nu.z / de0.z : 0.f; s += r > 0.f ? r : 0.f;
        r = de0.w > 0.f ? nu.w / de0.w : 0.f; s += r > 0.f ? r : 0.f;
    }
    d_h1s[i] = 0.25f * s;
}

// ---------------- combine 1: h2s ----------------------------------------------
__global__ void k_combine1(int n) {
    int i = blockIdx.x * blockDim.x + threadIdx.x;
    if (i >= n) return;
    float4 nu = d_num1[i];
    float4 de = d_den1[i];
    float s = 0.f, r;
    r = de.x > 0.f ? nu.x / de.x : 0.f; s += r > 0.f ? r : 0.f;
    r = de.y > 0.f ? nu.y / de.y : 0.f; s += r > 0.f ? r : 0.f;
    r = de.z > 0.f ? nu.z / de.z : 0.f; s += r > 0.f ? r : 0.f;
    r = de.w > 0.f ? nu.w / de.w : 0.f; s += r > 0.f ? r : 0.f;
    d_h2s[i] = 0.25f * s;
}

// ---------------- combine 2: final epilogue ------------------------------------
__global__ void k_combine2(int n, const float* __restrict__ centrality,
                           const float* __restrict__ gamma,
                           const float* __restrict__ beta,
                           float* __restrict__ out) {
    int i = blockIdx.x * blockDim.x + threadIdx.x;
    if (i >= n) return;
    float4 nu = d_num2[i];
    float4 de = d_den2[i];
    float c = centrality[i];
    float s = 0.f, r;
    r = de.x > 0.f ? nu.x / de.x : 0.f; r = r > 0.f ? r : 0.f;
    s += (c * __ldg(&gamma[0]) + __ldg(&beta[0])) * r;
    r = de.y > 0.f ? nu.y / de.y : 0.f; r = r > 0.f ? r : 0.f;
    s += (c * __ldg(&gamma[1]) + __ldg(&beta[1])) * r;
    r = de.z > 0.f ? nu.z / de.z : 0.f; r = r > 0.f ? r : 0.f;
    s += (c * __ldg(&gamma[2]) + __ldg(&beta[2])) * r;
    r = de.w > 0.f ? nu.w / de.w : 0.f; r = r > 0.f ? r : 0.f;
    s += (c * __ldg(&gamma[3]) + __ldg(&beta[3])) * r;
    float v = 0.25f * s;
    out[i] = (v > 0.f) ? v : 0.01f * v;
}

// ---------------- launch -------------------------------------------------------
extern "C" void kernel_launch(void* const* d_in, const int* in_sizes, int n_in,
                              void* d_out, int out_size) {
    const float* inputs     = (const float*)d_in[0];
    const float* centrality = (const float*)d_in[1];
    const float* W1         = (const float*)d_in[2];
    const float* b1         = (const float*)d_in[3];
    const float* W2         = (const float*)d_in[4];
    const float* b2         = (const float*)d_in[5];
    const float* rel_emb    = (const float*)d_in[6];
    const float* W_pred     = (const float*)d_in[7];
    const float* gamma      = (const float*)d_in[8];
    const float* beta       = (const float*)d_in[9];
    const int*   et         = (const int*)d_in[10];
    const int*   src        = (const int*)d_in[11];
    const int*   dst        = (const int*)d_in[12];

    const int n = in_sizes[1];          // N
    const int e = in_sizes[10];         // E
    float* out = (float*)d_out;

    const int EB = (e + 255) / 256;
    const int NB = (n + 255) / 256;

    k_tables<<<3, 256>>>(rel_emb, W_pred);
    k_zero<<<2048, 256>>>(n);
    k_mlp<<<dim3((n + 63) / 64, NH), 128>>>(inputs, W1, b1, W2, b2, n);

    // layer 0
    k_edge0<<<EB, 256>>>(et, src, dst, e);
    k_combine0<<<NB, 256>>>(n);

    // layer 1
    k_edgeS<<<EB, 256>>>(et, src, dst, e, 0);
    k_combine1<<<NB, 256>>>(n);

    // layer 2 + epilogue
    k_edgeS<<<EB, 256>>>(et, src, dst, e, 1);
    k_combine2<<<NB, 256>>>(n, centrality, gamma, beta, out);
}

// round 6
// speedup vs baseline: 1.5775x; 1.1801x over previous
#include <cuda_runtime.h>

#define N_MAX   100000
#define NH      4
#define HID     64
#define INDIM   128
#define REL     50
#define PD      16
#define CW      13          // ceil(REL/4) packed-count words per node

typedef unsigned long long ull;

// ---------------- scratch (device globals; no allocation allowed) -------------
__device__ __align__(16) float  d_w[3 * REL * NH];   // exp(leaky(rel_emb@W_pred)) per layer
__device__ __align__(16) float4 d_h0[N_MAX];         // MLP output (N,4)
__device__ unsigned d_cntp[N_MAX * CW];              // byte-packed type histogram
__device__ __align__(16) float4 d_num0[N_MAX];
__device__ __align__(16) float4 d_num1[N_MAX];
__device__ __align__(16) float4 d_num2[N_MAX];
__device__ __align__(16) float4 d_den1[N_MAX];
__device__ __align__(16) float4 d_den2[N_MAX];
__device__ float d_h1s[N_MAX];
__device__ float d_h2s[N_MAX];

// ---------------- packed f32x2 helpers -----------------------------------------
__device__ __forceinline__ ull pack2(float x, float y) {
    ull r; asm("mov.b64 %0,{%1,%2};" : "=l"(r) : "f"(x), "f"(y)); return r;
}
__device__ __forceinline__ void fma2(ull& d, ull a, ull b) {
    asm("fma.rn.f32x2 %0, %1, %2, %0;" : "+l"(d) : "l"(a), "l"(b));
}
__device__ __forceinline__ void unpack2(ull v, float& x, float& y) {
    asm("mov.b64 {%0,%1},%2;" : "=f"(x), "=f"(y) : "l"(v));
}

// ---------------- init: zero scratch + attention tables (fused) ----------------
__global__ void k_init(const float* __restrict__ rel_emb,
                       const float* __restrict__ W_pred, int n) {
    int gt = blockIdx.x * blockDim.x + threadIdx.x;
    if (gt < 3 * REL * NH) {
        int l = gt / (REL * NH);
        int r = gt - l * (REL * NH);
        int t = r >> 2, h = r & 3;
        float acc = 0.f;
#pragma unroll
        for (int p = 0; p < PD; ++p)
            acc += rel_emb[t * PD + p] * W_pred[l * PD * NH + p * NH + h];
        float e = acc > 0.f ? acc : 0.2f * acc;
        d_w[gt] = expf(e);
    }
    int stride = gridDim.x * blockDim.x;
    int tot = n * CW;
    for (int i = gt; i < tot; i += stride) d_cntp[i] = 0u;
    float4 z = make_float4(0.f, 0.f, 0.f, 0.f);
    for (int i = gt; i < n; i += stride) {
        d_num0[i] = z; d_num1[i] = z; d_num2[i] = z;
    }
}

// ---------------- fused-heads node MLP ------------------------------------------
// C[n, 256] = inputs[n,128] @ W1f^T (W1f = 256x128), then per-head epilogue.
// Block: 256 threads, tile 64 nodes x 256 cols. Thread: 4 nodes x 16 cols,
// accumulated as packed f32x2 pairs (fma.rn.f32x2 = 2x FFMA issue density).
#define BN 64
#define BK 32
__global__ void __launch_bounds__(256, 2) k_mlp(
    const float* __restrict__ inputs, const float* __restrict__ W1,
    const float* __restrict__ b1, const float* __restrict__ W2,
    const float* __restrict__ b2, int n) {
    __shared__ __align__(16) float As[BK][BN + 4];    // [k][node]
    __shared__ __align__(16) float Bs[BK][260];       // [k][col]
    __shared__ float red[16][BN + 1];

    const int tid = threadIdx.x;
    const int tn  = tid & 15;      // node group (nodes tn*4 .. tn*4+3)
    const int tc  = tid >> 4;      // col group  (cols tc*16 .. tc*16+15)
    const int n0  = blockIdx.x * BN;

    ull acc[4][8];
#pragma unroll
    for (int i = 0; i < 4; ++i)
#pragma unroll
        for (int p = 0; p < 8; ++p) acc[i][p] = 0ull;

    for (int kc = 0; kc < INDIM; kc += BK) {
        // stage A (transposed): 64 nodes x 32 k
        {
            int nl = tid >> 2;
            int kq = (tid & 3) * 8;
            int node = n0 + nl;
            float4 v0 = make_float4(0.f, 0.f, 0.f, 0.f), v1 = v0;
            if (node < n) {
                const float4* gp =
                    (const float4*)&inputs[(size_t)node * INDIM + kc + kq];
                v0 = gp[0]; v1 = gp[1];
            }
            As[kq + 0][nl] = v0.x; As[kq + 1][nl] = v0.y;
            As[kq + 2][nl] = v0.z; As[kq + 3][nl] = v0.w;
            As[kq + 4][nl] = v1.x; As[kq + 5][nl] = v1.y;
            As[kq + 6][nl] = v1.z; As[kq + 7][nl] = v1.w;
        }
        // stage B (transposed): 256 cols x 32 k ; thread = one col row
        {
            const float4* gp = (const float4*)&W1[(size_t)tid * INDIM + kc];
#pragma unroll
            for (int q = 0; q < 8; ++q) {
                float4 v = gp[q];
                Bs[q * 4 + 0][tid] = v.x; Bs[q * 4 + 1][tid] = v.y;
                Bs[q * 4 + 2][tid] = v.z; Bs[q * 4 + 3][tid] = v.w;
            }
        }
        __syncthreads();
#pragma unroll 4
        for (int k = 0; k < BK; ++k) {
            float4 av = *(const float4*)&As[k][tn * 4];
            ull a0 = pack2(av.x, av.x);
            ull a1 = pack2(av.y, av.y);
            ull a2 = pack2(av.z, av.z);
            ull a3 = pack2(av.w, av.w);
            const ulonglong2* bp = (const ulonglong2*)&Bs[k][tc * 16];
#pragma unroll
            for (int q = 0; q < 4; ++q) {
                ulonglong2 bv = bp[q];
                fma2(acc[0][2 * q + 0], a0, bv.x);
                fma2(acc[0][2 * q + 1], a0, bv.y);
                fma2(acc[1][2 * q + 0], a1, bv.x);
                fma2(acc[1][2 * q + 1], a1, bv.y);
                fma2(acc[2][2 * q + 0], a2, bv.x);
                fma2(acc[2][2 * q + 1], a2, bv.y);
                fma2(acc[3][2 * q + 0], a3, bv.x);
                fma2(acc[3][2 * q + 1], a3, bv.y);
            }
        }
        __syncthreads();
    }

    // epilogue: relu(+b1) * W2, partial sums over this thread's 16 cols
    float partial[4] = {0.f, 0.f, 0.f, 0.f};
#pragma unroll
    for (int p = 0; p < 8; ++p) {
        int col = tc * 16 + 2 * p;
        float bb0 = __ldg(&b1[col]), bb1 = __ldg(&b1[col + 1]);
        float w20 = __ldg(&W2[col]), w21 = __ldg(&W2[col + 1]);
#pragma unroll
        for (int i = 0; i < 4; ++i) {
            float lo, hi;
            unpack2(acc[i][p], lo, hi);
            lo += bb0; hi += bb1;
            lo = lo > 0.f ? lo : 0.f;
            hi = hi > 0.f ? hi : 0.f;
            partial[i] += lo * w20 + hi * w21;
        }
    }
#pragma unroll
    for (int i = 0; i < 4; ++i) red[tc][tn * 4 + i] = partial[i];
    __syncthreads();
    {
        int nl = tid & 63, hd = tid >> 6;   // head hd covers tc in [4hd, 4hd+4)
        float s = red[4 * hd + 0][nl] + red[4 * hd + 1][nl] +
                  red[4 * hd + 2][nl] + red[4 * hd + 3][nl];
        int node = n0 + nl;
        if (node < n) ((float*)d_h0)[node * NH + hd] = s + __ldg(&b2[hd]);
    }
}

// ---------------- layer 0 edge pass: packed histogram + vec4 numerators -------
__global__ void k_edge0(const int* __restrict__ et, const int* __restrict__ src,
                        const int* __restrict__ dst, int e) {
    __shared__ float4 w0[REL];
    if (threadIdx.x < REL) w0[threadIdx.x] = ((const float4*)d_w)[threadIdx.x];
    __syncthreads();
    int i = blockIdx.x * blockDim.x + threadIdx.x;
    if (i >= e) return;
    int t = et[i], s = src[i], d = dst[i];
    atomicAdd(&d_cntp[d * CW + (t >> 2)], 1u << (8 * (t & 3)));
    float4 hs = d_h0[s];
    float4 wv = w0[t];
    atomicAdd(&d_num0[d],
              make_float4(wv.x * hs.x, wv.y * hs.y, wv.z * hs.z, wv.w * hs.w));
}

// ---------------- layers 1/2 edge pass: scalar gather, vec4 scatter -----------
template <int WHICH>
__global__ void k_edgeS(const int* __restrict__ et, const int* __restrict__ src,
                        const int* __restrict__ dst, int e) {
    __shared__ float4 w[REL];
    if (threadIdx.x < REL)
        w[threadIdx.x] = ((const float4*)d_w)[(WHICH ? 2 : 1) * REL + threadIdx.x];
    __syncthreads();
    int i = blockIdx.x * blockDim.x + threadIdx.x;
    if (i >= e) return;
    int t = et[i], d = dst[i];
    float hs = WHICH ? d_h2s[src[i]] : d_h1s[src[i]];
    float4 wv = w[t];
    float4* numl = WHICH ? d_num2 : d_num1;
    atomicAdd(&numl[d], make_float4(wv.x * hs, wv.y * hs, wv.z * hs, wv.w * hs));
}

// ---------------- combine 0: dens for ALL layers from histogram + h1s ---------
__global__ void k_combine0(int n) {
    __shared__ float4 w[3 * REL];
    if (threadIdx.x < 3 * REL) w[threadIdx.x] = ((const float4*)d_w)[threadIdx.x];
    __syncthreads();
    int i = blockIdx.x * blockDim.x + threadIdx.x;
    if (i >= n) return;
    float4 de0 = make_float4(0.f, 0.f, 0.f, 0.f);
    float4 de1 = de0, de2 = de0;
#pragma unroll
    for (int j = 0; j < CW; ++j) {
        unsigned cw = d_cntp[i * CW + j];
#pragma unroll
        for (int b = 0; b < 4; ++b) {
            int t = j * 4 + b;
            if (t >= REL) break;
            float c = (float)((cw >> (8 * b)) & 0xffu);
            float4 w0 = w[t], w1 = w[REL + t], w2 = w[2 * REL + t];
            de0.x += c * w0.x; de0.y += c * w0.y; de0.z += c * w0.z; de0.w += c * w0.w;
            de1.x += c * w1.x; de1.y += c * w1.y; de1.z += c * w1.z; de1.w += c * w1.w;
            de2.x += c * w2.x; de2.y += c * w2.y; de2.z += c * w2.z; de2.w += c * w2.w;
        }
    }
    d_den1[i] = de1;
    d_den2[i] = de2;
    float4 nu = d_num0[i];
    float s = 0.f, r;
    r = de0.x > 0.f ? nu.x / de0.x : 0.f; s += r > 0.f ? r : 0.f;
    r = de0.y > 0.f ? nu.y / de0.y : 0.f; s += r > 0.f ? r : 0.f;
    r = de0.z > 0.f ? nu.z / de0.z : 0.f; s += r > 0.f ? r : 0.f;
    r = de0.w > 0.f ? nu.w / de0.w : 0.f; s += r > 0.f ? r : 0.f;
    d_h1s[i] = 0.25f * s;
}

// ---------------- combine 1: h2s ----------------------------------------------
__global__ void k_combine1(int n) {
    int i = blockIdx.x * blockDim.x + threadIdx.x;
    if (i >= n) return;
    float4 nu = d_num1[i];
    float4 de = d_den1[i];
    float s = 0.f, r;
    r = de.x > 0.f ? nu.x / de.x : 0.f; s += r > 0.f ? r : 0.f;
    r = de.y > 0.f ? nu.y / de.y : 0.f; s += r > 0.f ? r : 0.f;
    r = de.z > 0.f ? nu.z / de.z : 0.f; s += r > 0.f ? r : 0.f;
    r = de.w > 0.f ? nu.w / de.w : 0.f; s += r > 0.f ? r : 0.f;
    d_h2s[i] = 0.25f * s;
}

// ---------------- combine 2: final epilogue ------------------------------------
__global__ void k_combine2(int n, const float* __restrict__ centrality,
                           const float* __restrict__ gamma,
                           const float* __restrict__ beta,
                           float* __restrict__ out) {
    int i = blockIdx.x * blockDim.x + threadIdx.x;
    if (i >= n) return;
    float4 nu = d_num2[i];
    float4 de = d_den2[i];
    float c = centrality[i];
    float s = 0.f, r;
    r = de.x > 0.f ? nu.x / de.x : 0.f; r = r > 0.f ? r : 0.f;
    s += (c * __ldg(&gamma[0]) + __ldg(&beta[0])) * r;
    r = de.y > 0.f ? nu.y / de.y : 0.f; r = r > 0.f ? r : 0.f;
    s += (c * __ldg(&gamma[1]) + __ldg(&beta[1])) * r;
    r = de.z > 0.f ? nu.z / de.z : 0.f; r = r > 0.f ? r : 0.f;
    s += (c * __ldg(&gamma[2]) + __ldg(&beta[2])) * r;
    r = de.w > 0.f ? nu.w / de.w : 0.f; r = r > 0.f ? r : 0.f;
    s += (c * __ldg(&gamma[3]) + __ldg(&beta[3])) * r;
    float v = 0.25f * s;
    out[i] = (v > 0.f) ? v : 0.01f * v;
}

// ---------------- launch -------------------------------------------------------
extern "C" void kernel_launch(void* const* d_in, const int* in_sizes, int n_in,
                              void* d_out, int out_size) {
    const float* inputs     = (const float*)d_in[0];
    const float* centrality = (const float*)d_in[1];
    const float* W1         = (const float*)d_in[2];
    const float* b1         = (const float*)d_in[3];
    const float* W2         = (const float*)d_in[4];
    const float* b2         = (const float*)d_in[5];
    const float* rel_emb    = (const float*)d_in[6];
    const float* W_pred     = (const float*)d_in[7];
    const float* gamma      = (const float*)d_in[8];
    const float* beta       = (const float*)d_in[9];
    const int*   et         = (const int*)d_in[10];
    const int*   src        = (const int*)d_in[11];
    const int*   dst        = (const int*)d_in[12];

    const int n = in_sizes[1];          // N
    const int e = in_sizes[10];         // E
    float* out = (float*)d_out;

    const int EB = (e + 255) / 256;
    const int NB = (n + 255) / 256;

    k_init<<<2048, 256>>>(rel_emb, W_pred, n);
    k_mlp<<<(n + BN - 1) / BN, 256>>>(inputs, W1, b1, W2, b2, n);

    // layer 0
    k_edge0<<<EB, 256>>>(et, src, dst, e);
    k_combine0<<<NB, 256>>>(n);

    // layer 1
    k_edgeS<0><<<EB, 256>>>(et, src, dst, e);
    k_combine1<<<NB, 256>>>(n);

    // layer 2 + epilogue
    k_edgeS<1><<<EB, 256>>>(et, src, dst, e);
    k_combine2<<<NB, 256>>>(n, centrality, gamma, beta, out);
}

// round 8
// speedup vs baseline: 2.3278x; 1.4757x over previous
#include <cuda_runtime.h>
#include <cuda_bf16.h>
#include <cstdint>

#define N_MAX   100000
#define NH      4
#define HID     64
#define INDIM   128
#define REL     50
#define PD      16
#define CW      13          // ceil(REL/4) packed-count words per node

typedef unsigned long long ull;

// ---------------- scratch (device globals; no allocation allowed) -------------
__device__ __align__(16) float  d_w[3 * REL * NH];   // exp(leaky(rel_emb@W_pred)) per layer
__device__ __align__(16) float4 d_h0[N_MAX];         // MLP output (N,4)
__device__ unsigned d_cntp[N_MAX * CW];              // byte-packed type histogram
__device__ __align__(16) float4 d_num0[N_MAX];
__device__ __align__(16) float4 d_num1[N_MAX];
__device__ __align__(16) float4 d_num2[N_MAX];
__device__ __align__(16) float4 d_den1[N_MAX];
__device__ __align__(16) float4 d_den2[N_MAX];
__device__ float d_h1s[N_MAX];
__device__ float d_h2s[N_MAX];

// ---------------- init: zero scratch + attention tables (fused) ----------------
__global__ void k_init(const float* __restrict__ rel_emb,
                       const float* __restrict__ W_pred, int n) {
    int gt = blockIdx.x * blockDim.x + threadIdx.x;
    if (gt < 3 * REL * NH) {
        int l = gt / (REL * NH);
        int r = gt - l * (REL * NH);
        int t = r >> 2, h = r & 3;
        float acc = 0.f;
#pragma unroll
        for (int p = 0; p < PD; ++p)
            acc += rel_emb[t * PD + p] * W_pred[l * PD * NH + p * NH + h];
        float e = acc > 0.f ? acc : 0.2f * acc;
        d_w[gt] = expf(e);
    }
    int stride = gridDim.x * blockDim.x;
    int tot = n * CW;
    for (int i = gt; i < tot; i += stride) d_cntp[i] = 0u;
    float4 z = make_float4(0.f, 0.f, 0.f, 0.f);
    for (int i = gt; i < n; i += stride) {
        d_num0[i] = z; d_num1[i] = z; d_num2[i] = z;
    }
}

// ================= HMMA (mma.sync) split-bf16 MLP ==============================
// C[128 nodes, 128 cols] per block via mma.m16n8k16 bf16, fp32 accum.
// D = Ah*Bh + Al*Bh + Ah*Bl  (split-bf16, ~1e-5 relative error).
// grid = (2 col-halves, ceil(n/128)); block = 256 (8 warps = 4M x 2N).
// smem: 4 matrices of 128 rows x 32 k bf16 (padded ld=40) + b1/W2 slices.

#define LDP    40                       // padded bf16 row stride
#define MATB   (128 * LDP * 2)          // 10240 bytes per matrix chunk
#define OFF_AH 0
#define OFF_AL MATB
#define OFF_BH (2 * MATB)
#define OFF_BL (3 * MATB)
#define OFF_B1 (4 * MATB)               // 40960: 128 floats
#define OFF_W2 (OFF_B1 + 512)
#define SM_TOT (OFF_W2 + 512)           // 41984 bytes (static smem, < 48KB)

__device__ __forceinline__ uint32_t smem_u32(const void* p) {
    uint32_t a;
    asm("{ .reg .u64 t; cvta.to.shared.u64 t, %1; cvt.u32.u64 %0, t; }"
        : "=r"(a) : "l"(p));
    return a;
}
__device__ __forceinline__ uint32_t pack_bf2(__nv_bfloat16 lo, __nv_bfloat16 hi) {
    return (uint32_t)__bfloat16_as_ushort(lo) |
           ((uint32_t)__bfloat16_as_ushort(hi) << 16);
}
#define LDSM_X4(R0, R1, R2, R3, ADDR)                                         \
    asm volatile("ldmatrix.sync.aligned.m8n8.x4.shared.b16 {%0,%1,%2,%3}, [%4];" \
                 : "=r"(R0), "=r"(R1), "=r"(R2), "=r"(R3) : "r"(ADDR))

__device__ __forceinline__ void mma_bf16(float* d, const uint32_t* a,
                                         const uint32_t* b) {
    asm volatile(
        "mma.sync.aligned.m16n8k16.row.col.f32.bf16.bf16.f32 "
        "{%0,%1,%2,%3}, {%4,%5,%6,%7}, {%8,%9}, {%0,%1,%2,%3};"
        : "+f"(d[0]), "+f"(d[1]), "+f"(d[2]), "+f"(d[3])
        : "r"(a[0]), "r"(a[1]), "r"(a[2]), "r"(a[3]), "r"(b[0]), "r"(b[1]));
}

__global__ void __launch_bounds__(256) k_mlp_mma(
    const float* __restrict__ inputs, const float* __restrict__ W1,
    const float* __restrict__ b1, const float* __restrict__ W2,
    const float* __restrict__ b2, int n) {
    __shared__ __align__(16) char sm[SM_TOT];
    const int tid = threadIdx.x;
    const int lane = tid & 31, wid = tid >> 5;
    const int mw = wid & 3, nw = wid >> 2;           // 4 M-warps x 2 N-warps
    const int xh = blockIdx.x;                       // col half (0/1)
    const int n0 = blockIdx.y * 128;

    float* b1s = (float*)(sm + OFF_B1);
    float* w2s = (float*)(sm + OFF_W2);
    if (tid < 128) {
        b1s[tid] = b1[xh * 128 + tid];
        w2s[tid] = W2[xh * 128 + tid];
    }

    float acc[2][8][4];
#pragma unroll
    for (int m = 0; m < 2; ++m)
#pragma unroll
        for (int t = 0; t < 8; ++t)
#pragma unroll
            for (int r = 0; r < 4; ++r) acc[m][t][r] = 0.f;

    const uint32_t sb = smem_u32(sm);
    // ldmatrix per-lane address components
    const int rowA = mw * 32 + (lane & 15);
    const int kA = (lane >> 4) * 8;
    uint32_t aof[2];
#pragma unroll
    for (int m = 0; m < 2; ++m)
        aof[m] = sb + OFF_AH + (uint32_t)(((rowA + m * 16) * LDP + kA) * 2);
    const int colB = nw * 64 + (lane >> 4) * 8 + (lane & 7);
    const int kB = ((lane >> 3) & 1) * 8;
    uint32_t bof[4];
#pragma unroll
    for (int t = 0; t < 4; ++t)
        bof[t] = sb + OFF_BH + (uint32_t)(((colB + t * 16) * LDP + kB) * 2);

    const int sr = tid >> 1;              // staging row 0..127
    const int skb = (tid & 1) * 16;       // staging k offset (16 floats each)

    for (int kc = 0; kc < 4; ++kc) {      // K chunks of 32
        // ---- stage A (nodes) hi/lo ----
        {
            int node = n0 + sr;
            const float* p = inputs + (size_t)node * INDIM + kc * 32 + skb;
            uint32_t* ah = (uint32_t*)(sm + OFF_AH + (sr * LDP + skb) * 2);
            uint32_t* al = (uint32_t*)(sm + OFF_AL + (sr * LDP + skb) * 2);
            bool ok = node < n;
#pragma unroll
            for (int j = 0; j < 16; j += 4) {
                float4 v = ok ? *(const float4*)(p + j)
                              : make_float4(0.f, 0.f, 0.f, 0.f);
                __nv_bfloat16 hx = __float2bfloat16(v.x);
                __nv_bfloat16 hy = __float2bfloat16(v.y);
                __nv_bfloat16 hz = __float2bfloat16(v.z);
                __nv_bfloat16 hw = __float2bfloat16(v.w);
                ah[j / 2]     = pack_bf2(hx, hy);
                ah[j / 2 + 1] = pack_bf2(hz, hw);
                al[j / 2] = pack_bf2(__float2bfloat16(v.x - __bfloat162float(hx)),
                                     __float2bfloat16(v.y - __bfloat162float(hy)));
                al[j / 2 + 1] =
                    pack_bf2(__float2bfloat16(v.z - __bfloat162float(hz)),
                             __float2bfloat16(v.w - __bfloat162float(hw)));
            }
        }
        // ---- stage B = W1 rows (this block's 128 cols) hi/lo ----
        {
            const float* q =
                W1 + (size_t)(xh * 128 + sr) * INDIM + kc * 32 + skb;
            uint32_t* bh = (uint32_t*)(sm + OFF_BH + (sr * LDP + skb) * 2);
            uint32_t* bl = (uint32_t*)(sm + OFF_BL + (sr * LDP + skb) * 2);
#pragma unroll
            for (int j = 0; j < 16; j += 4) {
                float4 v = *(const float4*)(q + j);
                __nv_bfloat16 hx = __float2bfloat16(v.x);
                __nv_bfloat16 hy = __float2bfloat16(v.y);
                __nv_bfloat16 hz = __float2bfloat16(v.z);
                __nv_bfloat16 hw = __float2bfloat16(v.w);
                bh[j / 2]     = pack_bf2(hx, hy);
                bh[j / 2 + 1] = pack_bf2(hz, hw);
                bl[j / 2] = pack_bf2(__float2bfloat16(v.x - __bfloat162float(hx)),
                                     __float2bfloat16(v.y - __bfloat162float(hy)));
                bl[j / 2 + 1] =
                    pack_bf2(__float2bfloat16(v.z - __bfloat162float(hz)),
                             __float2bfloat16(v.w - __bfloat162float(hw)));
            }
        }
        __syncthreads();

#pragma unroll
        for (int pass = 0; pass < 3; ++pass) {
            uint32_t ab = (pass == 1) ? (uint32_t)MATB : 0u;   // Al vs Ah
            uint32_t bb = (pass == 2) ? (uint32_t)MATB : 0u;   // Bl vs Bh
#pragma unroll
            for (int ks = 0; ks < 2; ++ks) {
                uint32_t a[2][4], b[8][2];
                LDSM_X4(a[0][0], a[0][1], a[0][2], a[0][3],
                        aof[0] + ab + ks * 32);
                LDSM_X4(a[1][0], a[1][1], a[1][2], a[1][3],
                        aof[1] + ab + ks * 32);
#pragma unroll
                for (int t = 0; t < 4; ++t) {
                    uint32_t r0, r1, r2, r3;
                    LDSM_X4(r0, r1, r2, r3, bof[t] + bb + ks * 32);
                    b[2 * t][0] = r0; b[2 * t][1] = r1;
                    b[2 * t + 1][0] = r2; b[2 * t + 1][1] = r3;
                }
#pragma unroll
                for (int m = 0; m < 2; ++m)
#pragma unroll
                    for (int t = 0; t < 8; ++t) mma_bf16(acc[m][t], a[m], b[t]);
            }
        }
        __syncthreads();
    }

    // ---- epilogue: relu(C + b1) * W2, reduce over this warp's 64-col head ----
    float rs[2][2] = {{0.f, 0.f}, {0.f, 0.f}};
#pragma unroll
    for (int t = 0; t < 8; ++t) {
        int c = nw * 64 + t * 8 + (lane & 3) * 2;
        float bb0 = b1s[c], bb1 = b1s[c + 1];
        float ww0 = w2s[c], ww1 = w2s[c + 1];
#pragma unroll
        for (int m = 0; m < 2; ++m) {
            float v;
            v = acc[m][t][0] + bb0; v = v > 0.f ? v : 0.f; rs[m][0] += v * ww0;
            v = acc[m][t][1] + bb1; v = v > 0.f ? v : 0.f; rs[m][0] += v * ww1;
            v = acc[m][t][2] + bb0; v = v > 0.f ? v : 0.f; rs[m][1] += v * ww0;
            v = acc[m][t][3] + bb1; v = v > 0.f ? v : 0.f; rs[m][1] += v * ww1;
        }
    }
#pragma unroll
    for (int m = 0; m < 2; ++m)
#pragma unroll
        for (int hh = 0; hh < 2; ++hh) {
            rs[m][hh] += __shfl_xor_sync(0xffffffffu, rs[m][hh], 1);
            rs[m][hh] += __shfl_xor_sync(0xffffffffu, rs[m][hh], 2);
        }
    if ((lane & 3) == 0) {
        int head = xh * 2 + nw;
        float bias = __ldg(&b2[head]);
#pragma unroll
        for (int m = 0; m < 2; ++m) {
            int node = n0 + mw * 32 + m * 16 + (lane >> 2);
            if (node < n)
                ((float*)d_h0)[node * NH + head] = rs[m][0] + bias;
            if (node + 8 < n)
                ((float*)d_h0)[(node + 8) * NH + head] = rs[m][1] + bias;
        }
    }
}

// ---------------- layer 0 edge pass: packed histogram + vec4 numerators -------
__global__ void k_edge0(const int* __restrict__ et, const int* __restrict__ src,
                        const int* __restrict__ dst, int e) {
    __shared__ float4 w0[REL];
    if (threadIdx.x < REL) w0[threadIdx.x] = ((const float4*)d_w)[threadIdx.x];
    __syncthreads();
    int i = blockIdx.x * blockDim.x + threadIdx.x;
    if (i >= e) return;
    int t = et[i], s = src[i], d = dst[i];
    atomicAdd(&d_cntp[d * CW + (t >> 2)], 1u << (8 * (t & 3)));
    float4 hs = d_h0[s];
    float4 wv = w0[t];
    atomicAdd(&d_num0[d],
              make_float4(wv.x * hs.x, wv.y * hs.y, wv.z * hs.z, wv.w * hs.w));
}

// ---------------- layers 1/2 edge pass: scalar gather, vec4 scatter -----------
template <int WHICH>
__global__ void k_edgeS(const int* __restrict__ et, const int* __restrict__ src,
                        const int* __restrict__ dst, int e) {
    __shared__ float4 w[REL];
    if (threadIdx.x < REL)
        w[threadIdx.x] = ((const float4*)d_w)[(WHICH ? 2 : 1) * REL + threadIdx.x];
    __syncthreads();
    int i = blockIdx.x * blockDim.x + threadIdx.x;
    if (i >= e) return;
    int t = et[i], d = dst[i];
    float hs = WHICH ? d_h2s[src[i]] : d_h1s[src[i]];
    float4 wv = w[t];
    float4* numl = WHICH ? d_num2 : d_num1;
    atomicAdd(&numl[d], make_float4(wv.x * hs, wv.y * hs, wv.z * hs, wv.w * hs));
}

// ---------------- combine 0: dens for ALL layers from histogram + h1s ---------
__global__ void k_combine0(int n) {
    __shared__ float4 w[3 * REL];
    if (threadIdx.x < 3 * REL) w[threadIdx.x] = ((const float4*)d_w)[threadIdx.x];
    __syncthreads();
    int i = blockIdx.x * blockDim.x + threadIdx.x;
    if (i >= n) return;
    float4 de0 = make_float4(0.f, 0.f, 0.f, 0.f);
    float4 de1 = de0, de2 = de0;
#pragma unroll
    for (int j = 0; j < CW; ++j) {
        unsigned cw = d_cntp[i * CW + j];
#pragma unroll
        for (int b = 0; b < 4; ++b) {
            int t = j * 4 + b;
            if (t >= REL) break;
            float c = (float)((cw >> (8 * b)) & 0xffu);
            float4 w0 = w[t], w1 = w[REL + t], w2 = w[2 * REL + t];
            de0.x += c * w0.x; de0.y += c * w0.y; de0.z += c * w0.z; de0.w += c * w0.w;
            de1.x += c * w1.x; de1.y += c * w1.y; de1.z += c * w1.z; de1.w += c * w1.w;
            de2.x += c * w2.x; de2.y += c * w2.y; de2.z += c * w2.z; de2.w += c * w2.w;
        }
    }
    d_den1[i] = de1;
    d_den2[i] = de2;
    float4 nu = d_num0[i];
    float s = 0.f, r;
    r = de0.x > 0.f ? nu.x / de0.x : 0.f; s += r > 0.f ? r : 0.f;
    r = de0.y > 0.f ? nu.y / de0.y : 0.f; s += r > 0.f ? r : 0.f;
    r = de0.z > 0.f ? nu.z / de0.z : 0.f; s += r > 0.f ? r : 0.f;
    r = de0.w > 0.f ? nu.w / de0.w : 0.f; s += r > 0.f ? r : 0.f;
    d_h1s[i] = 0.25f * s;
}

// ---------------- combine 1: h2s ----------------------------------------------
__global__ void k_combine1(int n) {
    int i = blockIdx.x * blockDim.x + threadIdx.x;
    if (i >= n) return;
    float4 nu = d_num1[i];
    float4 de = d_den1[i];
    float s = 0.f, r;
    r = de.x > 0.f ? nu.x / de.x : 0.f; s += r > 0.f ? r : 0.f;
    r = de.y > 0.f ? nu.y / de.y : 0.f; s += r > 0.f ? r : 0.f;
    r = de.z > 0.f ? nu.z / de.z : 0.f; s += r > 0.f ? r : 0.f;
    r = de.w > 0.f ? nu.w / de.w : 0.f; s += r > 0.f ? r : 0.f;
    d_h2s[i] = 0.25f * s;
}

// ---------------- combine 2: final epilogue ------------------------------------
__global__ void k_combine2(int n, const float* __restrict__ centrality,
                           const float* __restrict__ gamma,
                           const float* __restrict__ beta,
                           float* __restrict__ out) {
    int i = blockIdx.x * blockDim.x + threadIdx.x;
    if (i >= n) return;
    float4 nu = d_num2[i];
    float4 de = d_den2[i];
    float c = centrality[i];
    float s = 0.f, r;
    r = de.x > 0.f ? nu.x / de.x : 0.f; r = r > 0.f ? r : 0.f;
    s += (c * __ldg(&gamma[0]) + __ldg(&beta[0])) * r;
    r = de.y > 0.f ? nu.y / de.y : 0.f; r = r > 0.f ? r : 0.f;
    s += (c * __ldg(&gamma[1]) + __ldg(&beta[1])) * r;
    r = de.z > 0.f ? nu.z / de.z : 0.f; r = r > 0.f ? r : 0.f;
    s += (c * __ldg(&gamma[2]) + __ldg(&beta[2])) * r;
    r = de.w > 0.f ? nu.w / de.w : 0.f; r = r > 0.f ? r : 0.f;
    s += (c * __ldg(&gamma[3]) + __ldg(&beta[3])) * r;
    float v = 0.25f * s;
    out[i] = (v > 0.f) ? v : 0.01f * v;
}

// ---------------- launch -------------------------------------------------------
extern "C" void kernel_launch(void* const* d_in, const int* in_sizes, int n_in,
                              void* d_out, int out_size) {
    const float* inputs     = (const float*)d_in[0];
    const float* centrality = (const float*)d_in[1];
    const float* W1         = (const float*)d_in[2];
    const float* b1         = (const float*)d_in[3];
    const float* W2         = (const float*)d_in[4];
    const float* b2         = (const float*)d_in[5];
    const float* rel_emb    = (const float*)d_in[6];
    const float* W_pred     = (const float*)d_in[7];
    const float* gamma      = (const float*)d_in[8];
    const float* beta       = (const float*)d_in[9];
    const int*   et         = (const int*)d_in[10];
    const int*   src        = (const int*)d_in[11];
    const int*   dst        = (const int*)d_in[12];

    const int n = in_sizes[1];          // N
    const int e = in_sizes[10];         // E
    float* out = (float*)d_out;

    const int EB = (e + 255) / 256;
    const int NB = (n + 255) / 256;

    k_init<<<2048, 256>>>(rel_emb, W_pred, n);
    k_mlp_mma<<<dim3(2, (n + 127) / 128), 256>>>(inputs, W1, b1, W2, b2, n);

    // layer 0
    k_edge0<<<EB, 256>>>(et, src, dst, e);
    k_combine0<<<NB, 256>>>(n);

    // layer 1
    k_edgeS<0><<<EB, 256>>>(et, src, dst, e);
    k_combine1<<<NB, 256>>>(n);

    // layer 2 + epilogue
    k_edgeS<1><<<EB, 256>>>(et, src, dst, e);
    k_combine2<<<NB, 256>>>(n, centrality, gamma, beta, out);
}